// round 1
// baseline (speedup 1.0000x reference)
#include <cuda_runtime.h>

// HexaToParallelogram: out[bs, q, r] = hexa[bs, pix(q,r)] for valid hex cells,
// 0.0 for the corner (sentinel) cells. Input inner dim is 1039, only the first
// 1027 channels are used. Output inner dims are 37x37 = 1369.
//
// The hex lookup table is closed-form:
//   axial coords (q, r), q,r in [-18, 18], valid iff |q + r| <= 18.
//   pixels sorted lexicographically by (q, r):
//     count(q)  = 37 - |q|
//     prefix(q) = sum_{q' < q} count(q')
//       q <= 0: prefix = 19*(q+18) + (q+17)*(q+18)/2
//       q >  0: prefix = 495 + 37*q - q*(q-1)/2
//     r_min(q)  = (q <= 0) ? -18 - q : -18
//     pix(q,r)  = prefix(q) + (r - r_min(q))

#define W         37      // 2*HEX_RADIUS + 1
#define CELLS     1369    // 37*37
#define IN_STRIDE 1039
#define TPB       256
#define ROWS      4       // (b,s) rows handled per thread

__device__ __forceinline__ int src_index(int j) {
    // j in [0, 1369): j = (q+18)*37 + (r+18)
    int qi = j / W;           // constant divisor -> mul/shift
    int ri = j - qi * W;
    int q = qi - 18;
    int r = ri - 18;
    int s = q + r;
    if (s < -18 || s > 18) return -1;   // sentinel corner -> padding
    if (q <= 0) {
        // prefix + (r - (-18 - q))
        return 19 * (q + 18) + ((q + 17) * (q + 18)) / 2 + (r + 18 + q);
    } else {
        return 495 + 37 * q - (q * (q - 1)) / 2 + (r + 18);
    }
}

__global__ void __launch_bounds__(TPB)
hexa_gather_kernel(const float* __restrict__ hexa,
                   float* __restrict__ out,
                   int total_rows) {
    int j = blockIdx.x * TPB + threadIdx.x;
    if (j >= CELLS) return;

    int src = src_index(j);
    long row0 = (long)blockIdx.y * ROWS;

#pragma unroll
    for (int k = 0; k < ROWS; k++) {
        long row = row0 + k;
        if (row >= total_rows) break;
        float v = 0.0f;
        if (src >= 0) {
            v = __ldg(hexa + row * IN_STRIDE + src);
        }
        out[row * CELLS + j] = v;
    }
}

extern "C" void kernel_launch(void* const* d_in, const int* in_sizes, int n_in,
                              void* d_out, int out_size) {
    const float* hexa = (const float*)d_in[0];
    float* out = (float*)d_out;

    int total_rows = out_size / CELLS;            // 64*512 = 32768
    dim3 grid((CELLS + TPB - 1) / TPB,            // 6
              (total_rows + ROWS - 1) / ROWS);    // 8192
    hexa_gather_kernel<<<grid, TPB>>>(hexa, out, total_rows);
}

// round 2
// speedup vs baseline: 1.7016x; 1.7016x over previous
#include <cuda_runtime.h>

// HexaToParallelogram: out[bs, q, r] = hexa[bs, pix(q,r)] for valid hex cells
// (|q+r| <= 18), 0.0 for corner cells. In: [32768, 1039] fp32 (first 1027 used),
// out: [32768, 1369] fp32.
//
// Closed-form lookup (no table in gmem):
//   qi = j/37, ri = j%37, q = qi-18, r = ri-18, valid iff 18 <= qi+ri <= 54
//   q <= 0: pix = 19*qi + qi*(qi-1)/2 + (ri + qi - 18)
//   q >  0: pix = 495 + 37*q - q*(q-1)/2 + ri

#define W          37
#define CELLS      1369           // 37*37
#define IN_STRIDE  1039
#define TPB        256
#define R          8              // rows per block
#define IN_FLOATS  (R * IN_STRIDE)   // 8312  (== 0 mod 4)
#define OUT_FLOATS (R * CELLS)       // 10952 (== 0 mod 4)
#define OUT_VEC    (OUT_FLOATS / 4)  // 2738

__device__ __forceinline__ int src_index(int j) {
    int qi = j / W;              // constant divisor -> mulhi
    int ri = j - qi * W;
    int s = qi + ri;
    if (s < 18 || s > 54) return -1;   // padding corner
    int q = qi - 18;
    if (q <= 0) {
        return 19 * qi + (qi * (qi - 1)) / 2 + (ri + qi - 18);
    } else {
        return 495 + 37 * q - (q * (q - 1)) / 2 + ri;
    }
}

__global__ void __launch_bounds__(TPB)
hexa_stage_kernel(const float* __restrict__ hexa,
                  float* __restrict__ out) {
    __shared__ float s_in[IN_FLOATS];
    __shared__ short s_src[CELLS + 3];   // +pad

    const unsigned row0 = blockIdx.x * R;

    // Phase 1a: bulk copy 8 input rows, fully vectorized (aligned: 8*1039 % 4 == 0)
    const float4* __restrict__ gin = (const float4*)(hexa + (size_t)row0 * IN_STRIDE);
    float4* s_in4 = (float4*)s_in;
    #pragma unroll
    for (int i = threadIdx.x; i < IN_FLOATS / 4; i += TPB) {
        s_in4[i] = gin[i];
    }

    // Phase 1b: build src table (overlaps with load latency)
    for (int j = threadIdx.x; j < CELLS; j += TPB) {
        s_src[j] = (short)src_index(j);
    }
    __syncthreads();

    // Phase 2: vectorized output, gathers served from smem
    float4* __restrict__ gout = (float4*)(out + (size_t)row0 * CELLS);
    #pragma unroll 2
    for (int v = threadIdx.x; v < OUT_VEC; v += TPB) {
        int f = 4 * v;
        float4 o;
        float* op = (float*)&o;
        #pragma unroll
        for (int e = 0; e < 4; e++) {
            int fe = f + e;
            int lr = fe / CELLS;          // constant divisor
            int j  = fe - lr * CELLS;
            int src = s_src[j];
            op[e] = (src >= 0) ? s_in[lr * IN_STRIDE + src] : 0.0f;
        }
        gout[v] = o;
    }
}

// Fallback scalar kernel for any tail rows (total_rows % R != 0)
__global__ void __launch_bounds__(TPB)
hexa_tail_kernel(const float* __restrict__ hexa,
                 float* __restrict__ out,
                 int row_start, int total_rows) {
    int j = blockIdx.x * TPB + threadIdx.x;
    if (j >= CELLS) return;
    int src = src_index(j);
    for (int row = row_start + blockIdx.y; row < total_rows; row += gridDim.y) {
        float v = (src >= 0) ? __ldg(hexa + (size_t)row * IN_STRIDE + src) : 0.0f;
        out[(size_t)row * CELLS + j] = v;
    }
}

extern "C" void kernel_launch(void* const* d_in, const int* in_sizes, int n_in,
                              void* d_out, int out_size) {
    const float* hexa = (const float*)d_in[0];
    float* out = (float*)d_out;

    int total_rows = out_size / CELLS;       // 32768
    int full_blocks = total_rows / R;        // 4096
    if (full_blocks > 0) {
        hexa_stage_kernel<<<full_blocks, TPB>>>(hexa, out);
    }
    int done = full_blocks * R;
    if (done < total_rows) {
        dim3 grid((CELLS + TPB - 1) / TPB, total_rows - done);
        hexa_tail_kernel<<<grid, TPB>>>(hexa, out, done, total_rows);
    }
}